// round 6
// baseline (speedup 1.0000x reference)
#include <cuda_runtime.h>
#include <math.h>

#define BH   16          // batch*heads
#define NSEQ 2048
#define DH   64
#define MF   256         // feature dim
#define CH   64          // chunk length
#define NC   (NSEQ/CH)   // 32 chunks per head
#define CSUM (MF*DH + MF)
#define TOK  16

#define NORMALIZER 0.35355339059327373f  // 64^-0.25
#define RATIO      0.0625f               // 256^-0.5
#define EPSK       1e-4f
#define EPSD       1e-6f

#define QS 257   // padded row stride for q_s/k_s
#define SS 65    // padded row stride for S_s

__device__ float g_qp[BH*NSEQ*MF];     // phi(q)
__device__ float g_kp[BH*NSEQ*MF];     // pass1: xd-diag ; pass2: phi(k)
__device__ float g_kmax[BH];
__device__ float g_csum[BH*NC*CSUM];   // per-chunk [Ctx(256x64) | ksum(256)], later exclusive prefix

__device__ __forceinline__ void atomicMaxF(float* addr, float val) {
    int old = __float_as_int(*addr);
    while (val > __int_as_float(old)) {
        int assumed = old;
        old = atomicCAS((int*)addr, assumed, __float_as_int(val));
        if (old == assumed) break;
    }
}

__global__ void init_kernel() {
    if (threadIdx.x < BH) g_kmax[threadIdx.x] = -3.0e38f;
}

// One block = 16 tokens of one head. 256 threads, thread = feature m.
template<bool IS_Q>
__global__ __launch_bounds__(256) void proj_kernel(const float* __restrict__ x,
                                                   const float* __restrict__ proj) {
    int blk  = blockIdx.x;
    int head = blk / (NSEQ/TOK);
    int t0   = (blk % (NSEQ/TOK)) * TOK;
    int tid  = threadIdx.x;

    __shared__ float x_s[TOK*DH];
    __shared__ float diag_s[TOK];
    __shared__ float red_s[8];

    float4 pr[16];
    const float4* p4 = reinterpret_cast<const float4*>(proj + tid*DH);
#pragma unroll
    for (int j = 0; j < 16; j++) pr[j] = p4[j];

    const float* xb = x + ((size_t)head*NSEQ + t0)*DH;
    for (int i = tid; i < TOK*DH; i += 256) x_s[i] = NORMALIZER * xb[i];
    __syncthreads();
    if (tid < TOK) {
        float s = 0.f;
#pragma unroll
        for (int d = 0; d < DH; d++) { float vv = x_s[tid*DH + d]; s += vv*vv; }
        diag_s[tid] = 0.5f * s;
    }
    __syncthreads();

    float lmax = -3.0e38f;
    float* outp = (IS_Q ? g_qp : g_kp) + ((size_t)head*NSEQ + t0)*MF + tid;
    for (int t = 0; t < TOK; t++) {
        const float4* xs4 = reinterpret_cast<const float4*>(x_s + t*DH);
        float acc = 0.f;
#pragma unroll
        for (int j = 0; j < 16; j++) {
            float4 xv = xs4[j]; float4 pv = pr[j];
            acc += xv.x*pv.x; acc += xv.y*pv.y; acc += xv.z*pv.z; acc += xv.w*pv.w;
        }
        if (IS_Q) {
            float w = acc;
#pragma unroll
            for (int o = 16; o >= 1; o >>= 1) w = fmaxf(w, __shfl_xor_sync(0xffffffffu, w, o));
            if ((tid & 31) == 0) red_s[tid >> 5] = w;
            __syncthreads();
            float mx = red_s[0];
#pragma unroll
            for (int r = 1; r < 8; r++) mx = fmaxf(mx, red_s[r]);
            outp[t*MF] = RATIO * (__expf(acc - diag_s[t] - mx) + EPSK);
            __syncthreads();
        } else {
            lmax = fmaxf(lmax, acc);         // key max is over raw xd per head
            outp[t*MF] = acc - diag_s[t];    // store xd - diag, exp applied later
        }
    }
    if (!IS_Q) {
#pragma unroll
        for (int o = 16; o >= 1; o >>= 1) lmax = fmaxf(lmax, __shfl_xor_sync(0xffffffffu, lmax, o));
        if ((tid & 31) == 0) red_s[tid >> 5] = lmax;
        __syncthreads();
        if (tid == 0) {
            float mx = red_s[0];
            for (int r = 1; r < 8; r++) mx = fmaxf(mx, red_s[r]);
            atomicMaxF(&g_kmax[head], mx);
        }
    }
}

// One block = one (head, chunk). Finalizes phi(k) in-place and computes
// per-chunk Ctx = sum_t k_t v_t^T  and ksum = sum_t k_t.
__global__ __launch_bounds__(256) void chunksum_kernel(const float* __restrict__ v) {
    int head = blockIdx.x / NC;
    int c    = blockIdx.x % NC;
    int t0   = c*CH;
    int tid  = threadIdx.x;   // m
    __shared__ float v_s[CH*DH];
    const float* vb = v + ((size_t)head*NSEQ + t0)*DH;
    for (int i = tid; i < CH*DH; i += 256) v_s[i] = vb[i];
    float kmax = g_kmax[head];
    __syncthreads();

    float4 acc[16];
#pragma unroll
    for (int j = 0; j < 16; j++) acc[j] = make_float4(0.f,0.f,0.f,0.f);
    float ks = 0.f;
    float* kpb = g_kp + ((size_t)head*NSEQ + t0)*MF + tid;
    for (int t = 0; t < CH; t++) {
        float raw = kpb[(size_t)t*MF];
        float phi = RATIO * (__expf(raw - kmax) + EPSK);
        kpb[(size_t)t*MF] = phi;
        ks += phi;
        const float4* vv4 = reinterpret_cast<const float4*>(v_s + t*DH);
#pragma unroll
        for (int j = 0; j < 16; j++) {
            float4 vv = vv4[j];
            acc[j].x += phi*vv.x; acc[j].y += phi*vv.y;
            acc[j].z += phi*vv.z; acc[j].w += phi*vv.w;
        }
    }
    float* ob = g_csum + (size_t)(head*NC + c)*CSUM;
    float4* ob4 = reinterpret_cast<float4*>(ob + tid*DH);
#pragma unroll
    for (int j = 0; j < 16; j++) ob4[j] = acc[j];
    ob[MF*DH + tid] = ks;
}

// In-place exclusive prefix over chunks, one block per head.
__global__ __launch_bounds__(256) void prefix_kernel() {
    int head = blockIdx.x;
    float* base = g_csum + (size_t)head*NC*CSUM;
    for (int idx = threadIdx.x; idx < CSUM; idx += 256) {
        float run = 0.f;
#pragma unroll
        for (int cc = 0; cc < NC; cc++) {
            float t = base[(size_t)cc*CSUM + idx];
            base[(size_t)cc*CSUM + idx] = run;
            run += t;
        }
    }
}

// One block = one (head, chunk). out = (maskedS @ V + Q @ P) / den.
__global__ __launch_bounds__(256) void out_kernel(const float* __restrict__ v,
                                                  float* __restrict__ out) {
    int head = blockIdx.x / NC;
    int c    = blockIdx.x % NC;
    int t0   = c*CH;
    int tid  = threadIdx.x;

    extern __shared__ float sm[];
    float* q_s   = sm;                  // [64][257]
    float* k_s   = q_s + CH*QS;         // [64][257], later reused as P [256][64]
    float* v_s   = k_s + CH*QS;         // [64][64]
    float* S_s   = v_s + CH*DH;         // [64][65]
    float* s_s   = S_s + CH*SS;         // [256] prefix ksum
    float* den_s = s_s + MF;            // [64]

    const float* qg = g_qp + ((size_t)head*NSEQ + t0)*MF;
    const float* kg = g_kp + ((size_t)head*NSEQ + t0)*MF;
    for (int i = tid; i < CH*MF; i += 256) {
        int t = i >> 8; int m = i & 255;
        q_s[t*QS + m] = qg[i];
        k_s[t*QS + m] = kg[i];
    }
    const float* vb = v + ((size_t)head*NSEQ + t0)*DH;
    for (int i = tid; i < CH*DH; i += 256) v_s[i] = vb[i];
    if (tid < CH) den_s[tid] = 0.f;
    __syncthreads();

    // --- S = Qp @ Kp^T  (each thread: 4x4 tile) ---
    int ti = tid >> 4, tj = tid & 15;
    float sacc[4][4];
#pragma unroll
    for (int r = 0; r < 4; r++)
#pragma unroll
        for (int cc = 0; cc < 4; cc++) sacc[r][cc] = 0.f;

    for (int m = 0; m < MF; m++) {
        float qv[4], kv[4];
#pragma unroll
        for (int r = 0; r < 4; r++)  qv[r]  = q_s[(4*ti + r)*QS + m];
#pragma unroll
        for (int cc = 0; cc < 4; cc++) kv[cc] = k_s[(4*tj + cc)*QS + m];
#pragma unroll
        for (int r = 0; r < 4; r++)
#pragma unroll
            for (int cc = 0; cc < 4; cc++)
                sacc[r][cc] += qv[r]*kv[cc];
    }
    // causal mask + row sums (intra part of denominator)
#pragma unroll
    for (int r = 0; r < 4; r++) {
        int row = 4*ti + r;
        float rs = 0.f;
#pragma unroll
        for (int cc = 0; cc < 4; cc++) {
            int col = 4*tj + cc;
            float val = (col <= row) ? sacc[r][cc] : 0.f;
            S_s[row*SS + col] = val;
            rs += val;
        }
        atomicAdd(&den_s[row], rs);
    }
    __syncthreads();

    // stage prefix Ctx into k_s region + prefix ksum
    float* P_s = k_s;
    const float* pb = g_csum + (size_t)(head*NC + c)*CSUM;
    for (int i = tid; i < MF*DH; i += 256) P_s[i] = pb[i];
    if (tid < MF) s_s[tid] = pb[MF*DH + tid];
    __syncthreads();

    // --- out = S_s @ V + Q @ P ; den += q . (s_pref + eps) ---
    int oi = tid >> 2;
    int d0 = (tid & 3) * 16;
    float4 oa[4];
#pragma unroll
    for (int u = 0; u < 4; u++) oa[u] = make_float4(0.f,0.f,0.f,0.f);
    float dacc = 0.f;

    for (int m = 0; m < MF; m++) {
        float qv = q_s[oi*QS + m];
        dacc += qv * (s_s[m] + EPSD);
        const float4* Pr = reinterpret_cast<const float4*>(P_s + m*DH + d0);
#pragma unroll
        for (int u = 0; u < 4; u++) {
            float4 pv = Pr[u];
            oa[u].x += qv*pv.x; oa[u].y += qv*pv.y; oa[u].z += qv*pv.z; oa[u].w += qv*pv.w;
        }
    }
    for (int j = 0; j < CH; j++) {
        float sv = S_s[oi*SS + j];
        const float4* Vr = reinterpret_cast<const float4*>(v_s + j*DH + d0);
#pragma unroll
        for (int u = 0; u < 4; u++) {
            float4 vv = Vr[u];
            oa[u].x += sv*vv.x; oa[u].y += sv*vv.y; oa[u].z += sv*vv.z; oa[u].w += sv*vv.w;
        }
    }
    if ((tid & 3) == 0) den_s[oi] += dacc;   // unique writer per row after prior sync
    __syncthreads();

    float inv = 1.0f / den_s[oi];
    float4* og4 = reinterpret_cast<float4*>(out + ((size_t)head*NSEQ + t0 + oi)*DH + d0);
#pragma unroll
    for (int u = 0; u < 4; u++) {
        oa[u].x *= inv; oa[u].y *= inv; oa[u].z *= inv; oa[u].w *= inv;
        og4[u] = oa[u];
    }
}

extern "C" void kernel_launch(void* const* d_in, const int* in_sizes, int n_in,
                              void* d_out, int out_size) {
    const float* q    = (const float*)d_in[0];
    const float* k    = (const float*)d_in[1];
    const float* v    = (const float*)d_in[2];
    const float* proj = (const float*)d_in[3];
    float* out = (float*)d_out;

    size_t smem_out = (size_t)(CH*QS*2 + CH*DH + CH*SS + MF + CH) * sizeof(float);
    cudaFuncSetAttribute(out_kernel, cudaFuncAttributeMaxDynamicSharedMemorySize, (int)smem_out);

    init_kernel<<<1, 32>>>();
    proj_kernel<true ><<<BH*(NSEQ/TOK), 256>>>(q, proj);
    proj_kernel<false><<<BH*(NSEQ/TOK), 256>>>(k, proj);
    chunksum_kernel<<<BH*NC, 256>>>(v);
    prefix_kernel<<<BH, 256>>>();
    out_kernel<<<BH*NC, 256, smem_out>>>(v, out);
}

// round 8
// speedup vs baseline: 1.2123x; 1.2123x over previous
#include <cuda_runtime.h>
#include <math.h>

#define BH   16
#define NSEQ 2048
#define DH   64
#define MF   256
#define CH   64
#define NC   (NSEQ/CH)
#define CSUM (MF*DH + MF)
#define TOK  16

#define NORMALIZER 0.35355339059327373f  // 64^-0.25
#define RATIO      0.0625f               // 256^-0.5
#define EPSK       1e-4f
#define EPSD       1e-6f

#define QS 258   // even padded stride for q_s/k_s (f32x2 loads)
#define SS 65

typedef unsigned long long ull;

__device__ __align__(16) float g_qp[BH*NSEQ*MF];
__device__ __align__(16) float g_kp[BH*NSEQ*MF];
__device__ __align__(16) float g_kmax[BH];
__device__ __align__(16) float g_csum[BH*NC*CSUM];

__device__ __forceinline__ ull pack2(float lo, float hi) {
    ull r; asm("mov.b64 %0, {%1,%2};" : "=l"(r) : "f"(lo), "f"(hi)); return r;
}
__device__ __forceinline__ void fma2(ull& acc, ull a, ull b) {
    asm("fma.rn.f32x2 %0, %1, %2, %0;" : "+l"(acc) : "l"(a), "l"(b));
}
__device__ __forceinline__ float lohi(ull a) {
    float lo, hi; asm("mov.b64 {%0,%1}, %2;" : "=f"(lo), "=f"(hi) : "l"(a)); return lo + hi;
}
__device__ __forceinline__ void unpk(ull a, float& lo, float& hi) {
    asm("mov.b64 {%0,%1}, %2;" : "=f"(lo), "=f"(hi) : "l"(a));
}

__device__ __forceinline__ void atomicMaxF(float* addr, float val) {
    int old = __float_as_int(*addr);
    while (val > __int_as_float(old)) {
        int assumed = old;
        old = atomicCAS((int*)addr, assumed, __float_as_int(val));
        if (old == assumed) break;
    }
}

__global__ void init_kernel() {
    if (threadIdx.x < BH) g_kmax[threadIdx.x] = -3.0e38f;
}

// One block = 16 tokens of one head. 256 threads, thread = feature m.
template<bool IS_Q>
__global__ __launch_bounds__(256) void proj_kernel(const float* __restrict__ x,
                                                   const float* __restrict__ proj) {
    int blk  = blockIdx.x;
    int head = blk / (NSEQ/TOK);
    int t0   = (blk % (NSEQ/TOK)) * TOK;
    int tid  = threadIdx.x;
    int wid  = tid >> 5, lane = tid & 31;

    __shared__ __align__(16) float x_s[TOK*DH];
    __shared__ float diag_s[TOK];
    __shared__ float red_s[TOK*8];
    __shared__ float mx_s[TOK];

    // proj row for this feature, packed as 32 f32x2
    ull pr2[32];
    const ull* p8 = reinterpret_cast<const ull*>(proj + tid*DH);
#pragma unroll
    for (int j = 0; j < 32; j++) pr2[j] = p8[j];

    const float* xb = x + ((size_t)head*NSEQ + t0)*DH;
    for (int i = tid; i < TOK*DH; i += 256) x_s[i] = NORMALIZER * xb[i];
    __syncthreads();
    if (tid < TOK) {
        float s = 0.f;
#pragma unroll
        for (int d = 0; d < DH; d++) { float vv = x_s[tid*DH + d]; s += vv*vv; }
        diag_s[tid] = 0.5f * s;
    }
    __syncthreads();

    // 16 independent packed FMA chains: acc2[t] += x2[t][j] * p2[j]
    ull acc2[TOK];
#pragma unroll
    for (int t = 0; t < TOK; t++) acc2[t] = 0ull;
#pragma unroll 4
    for (int j = 0; j < 32; j++) {
        ull pv = pr2[j];
#pragma unroll
        for (int t = 0; t < TOK; t++) {
            ull xv = *reinterpret_cast<const ull*>(x_s + t*DH + 2*j);
            fma2(acc2[t], xv, pv);
        }
    }
    float a[TOK];
#pragma unroll
    for (int t = 0; t < TOK; t++) a[t] = lohi(acc2[t]);

    float* outp = (IS_Q ? g_qp : g_kp) + ((size_t)head*NSEQ + t0)*MF + tid;
    if (IS_Q) {
#pragma unroll
        for (int t = 0; t < TOK; t++) {
            float w = a[t];
#pragma unroll
            for (int o = 16; o >= 1; o >>= 1) w = fmaxf(w, __shfl_xor_sync(0xffffffffu, w, o));
            if (lane == 0) red_s[t*8 + wid] = w;
        }
        __syncthreads();
        if (tid < TOK) {
            float mx = red_s[tid*8];
#pragma unroll
            for (int r = 1; r < 8; r++) mx = fmaxf(mx, red_s[tid*8 + r]);
            mx_s[tid] = mx;
        }
        __syncthreads();
#pragma unroll
        for (int t = 0; t < TOK; t++)
            outp[t*MF] = RATIO * (__expf(a[t] - diag_s[t] - mx_s[t]) + EPSK);
    } else {
        float lm = a[0];
#pragma unroll
        for (int t = 1; t < TOK; t++) lm = fmaxf(lm, a[t]);
#pragma unroll
        for (int t = 0; t < TOK; t++) outp[t*MF] = a[t] - diag_s[t];
#pragma unroll
        for (int o = 16; o >= 1; o >>= 1) lm = fmaxf(lm, __shfl_xor_sync(0xffffffffu, lm, o));
        if (lane == 0) red_s[wid] = lm;
        __syncthreads();
        if (tid == 0) {
            float mx = red_s[0];
            for (int r = 1; r < 8; r++) mx = fmaxf(mx, red_s[r]);
            atomicMaxF(&g_kmax[head], mx);
        }
    }
}

// One block = one (head, chunk). 512 threads.
// Phase 1: bulk-load raw k, apply exp, stage phi in smem + write back.
// Phase 2: Ctx[m][d] = sum_t phi[t][m] * v[t][d] with packed f32x2 (32 d per thread).
__global__ __launch_bounds__(512) void chunksum_kernel(const float* __restrict__ v) {
    int head = blockIdx.x / NC;
    int c    = blockIdx.x % NC;
    int t0   = c*CH;
    int tid  = threadIdx.x;

    extern __shared__ __align__(16) float cs[];
    float* phi_s = cs;              // [64][256]
    float* v_s   = cs + CH*MF;      // [64][64]

    const float* vb = v + ((size_t)head*NSEQ + t0)*DH;
    for (int i = tid; i < CH*DH; i += 512) v_s[i] = vb[i];
    float kmax = g_kmax[head];

    float* kpb = g_kp + ((size_t)head*NSEQ + t0)*MF;
    for (int i = tid; i < CH*MF; i += 512) {
        float raw = kpb[i];
        float phi = RATIO * (__expf(raw - kmax) + EPSK);
        phi_s[i] = phi;
        kpb[i]   = phi;
    }
    __syncthreads();

    int m    = tid & 255;
    int half = tid >> 8;   // uniform per warp
    ull acc2[16];
#pragma unroll
    for (int j = 0; j < 16; j++) acc2[j] = 0ull;
    float ks = 0.f;

#pragma unroll 4
    for (int t = 0; t < CH; t++) {
        float ph = phi_s[t*MF + m];
        if (half == 0) ks += ph;
        ull p2 = pack2(ph, ph);
        const ull* v8 = reinterpret_cast<const ull*>(v_s + t*DH + half*32);
#pragma unroll
        for (int j = 0; j < 16; j++) fma2(acc2[j], p2, v8[j]);
    }
    float* ob = g_csum + (size_t)(head*NC + c)*CSUM;
    ull* dst = reinterpret_cast<ull*>(ob + m*DH + half*32);
#pragma unroll
    for (int j = 0; j < 16; j++) dst[j] = acc2[j];
    if (half == 0) ob[MF*DH + m] = ks;
}

// Exclusive prefix over chunks. grid (BH, 65), 256 threads: 1 idx/thread, 32 loads in flight.
__global__ __launch_bounds__(256) void prefix_kernel() {
    int head = blockIdx.x;
    int idx  = blockIdx.y*256 + threadIdx.x;   // 65*256 = 16640 = CSUM exactly
    float* base = g_csum + (size_t)head*NC*CSUM + idx;
    float vals[NC];
#pragma unroll
    for (int cc = 0; cc < NC; cc++) vals[cc] = base[(size_t)cc*CSUM];
    float run = 0.f;
#pragma unroll
    for (int cc = 0; cc < NC; cc++) { base[(size_t)cc*CSUM] = run; run += vals[cc]; }
}

// One block = one (head, chunk). 512 threads, warp-specialized.
__global__ __launch_bounds__(512) void out_kernel(const float* __restrict__ v,
                                                  float* __restrict__ out) {
    int head = blockIdx.x / NC;
    int c    = blockIdx.x % NC;
    int t0   = c*CH;
    int tid  = threadIdx.x;
    int warp = tid >> 5;

    extern __shared__ __align__(16) float sm[];
    float* q_s   = sm;                 // [64][258]
    float* k_s   = q_s + CH*QS;        // [64][258], XOR-swizzled f32x2 within row
    float* P_s   = k_s + CH*QS;        // [256][64] prefix Ctx
    float* v_s   = P_s + MF*DH;        // [64][64]
    float* S_s   = v_s + CH*DH;        // [64][65]
    float* s_s   = S_s + CH*SS;        // [256] prefix ksum
    float* den_s = s_s + MF;           // [64]

    const float* qg = g_qp + ((size_t)head*NSEQ + t0)*MF;
    const float* kg = g_kp + ((size_t)head*NSEQ + t0)*MF;
    for (int i = tid; i < CH*MF; i += 512) {
        int t = i >> 8; int m = i & 255;
        q_s[t*QS + m] = qg[i];
        int sw = ((m >> 1) ^ (t >> 4));
        k_s[t*QS + 2*sw + (m & 1)] = kg[i];
    }
    const float* pb = g_csum + (size_t)(head*NC + c)*CSUM;
    for (int i = tid; i < MF*DH; i += 512) P_s[i] = pb[i];
    const float* vb = v + ((size_t)head*NSEQ + t0)*DH;
    for (int i = tid; i < CH*DH; i += 512) v_s[i] = vb[i];
    if (tid < MF) s_s[tid] = pb[MF*DH + tid];
    if (tid < CH) den_s[tid] = 0.f;
    __syncthreads();

    ull oa[2][4];
    int r0 = 0, dg = 0;

    if (warp < 8) {
        // --- S = Q'K'^T, 256 threads, 4x4 tile, m-paired f32x2, swizzled k reads ---
        int ti = tid >> 4;    // rows 4ti..4ti+3
        int tj = tid & 15;    // cols 4tj..4tj+3
        ull acc2[4][4];
#pragma unroll
        for (int r = 0; r < 4; r++)
#pragma unroll
            for (int cc = 0; cc < 4; cc++) acc2[r][cc] = 0ull;

#pragma unroll 8
        for (int m2 = 0; m2 < MF/2; m2++) {
            ull q2[4], k2[4];
#pragma unroll
            for (int r = 0; r < 4; r++)
                q2[r] = *reinterpret_cast<const ull*>(q_s + (4*ti + r)*QS + 2*m2);
#pragma unroll
            for (int cc = 0; cc < 4; cc++) {
                int row = 4*tj + cc;
                k2[cc] = *reinterpret_cast<const ull*>(k_s + row*QS + 2*(m2 ^ (row >> 4)));
            }
#pragma unroll
            for (int r = 0; r < 4; r++)
#pragma unroll
                for (int cc = 0; cc < 4; cc++) fma2(acc2[r][cc], q2[r], k2[cc]);
        }
#pragma unroll
        for (int r = 0; r < 4; r++) {
            int row = 4*ti + r;
            float rs = 0.f;
#pragma unroll
            for (int cc = 0; cc < 4; cc++) {
                int col = 4*tj + cc;
                float val = (col <= row) ? lohi(acc2[r][cc]) : 0.f;
                S_s[row*SS + col] = val;
                rs += val;
            }
            atomicAdd(&den_s[row], rs);
        }
        // --- denominator inter part: q . (s_pref + eps), 4 threads per row ---
        int row = tid >> 2; int m0 = (tid & 3) * 64;
        float d1 = 0.f;
#pragma unroll 4
        for (int mm = 0; mm < 64; mm++) {
            int m = m0 + mm;
            d1 += q_s[row*QS + m] * (s_s[m] + EPSD);
        }
        atomicAdd(&den_s[row], d1);
    } else {
        // --- Q @ P, 256 threads: 2 rows x 8 d-floats each ---
        int idx = tid - 256;
        r0 = (idx >> 3) * 2;
        dg = (idx & 7) * 8;
#pragma unroll
        for (int u = 0; u < 4; u++) { oa[0][u] = 0ull; oa[1][u] = 0ull; }
#pragma unroll 4
        for (int m = 0; m < MF; m++) {
            float q0 = q_s[r0*QS + m];
            float q1 = q_s[(r0+1)*QS + m];
            ull qq0 = pack2(q0, q0);
            ull qq1 = pack2(q1, q1);
            const ull* Pr = reinterpret_cast<const ull*>(P_s + m*DH + dg);
#pragma unroll
            for (int u = 0; u < 4; u++) {
                ull pv = Pr[u];
                fma2(oa[0][u], qq0, pv);
                fma2(oa[1][u], qq1, pv);
            }
        }
    }
    __syncthreads();

    if (warp >= 8) {
        // --- add masked S @ V ---
#pragma unroll 4
        for (int j = 0; j < CH; j++) {
            float s0 = S_s[r0*SS + j];
            float s1 = S_s[(r0+1)*SS + j];
            ull ss0 = pack2(s0, s0);
            ull ss1 = pack2(s1, s1);
            const ull* Vr = reinterpret_cast<const ull*>(v_s + j*DH + dg);
#pragma unroll
            for (int u = 0; u < 4; u++) {
                ull vv = Vr[u];
                fma2(oa[0][u], ss0, vv);
                fma2(oa[1][u], ss1, vv);
            }
        }
        float inv0 = 1.0f / den_s[r0];
        float inv1 = 1.0f / den_s[r0+1];
#pragma unroll
        for (int r = 0; r < 2; r++) {
            float inv = r ? inv1 : inv0;
            float f[8];
#pragma unroll
            for (int u = 0; u < 4; u++) unpk(oa[r][u], f[2*u], f[2*u+1]);
            float4 w0 = make_float4(f[0]*inv, f[1]*inv, f[2]*inv, f[3]*inv);
            float4 w1 = make_float4(f[4]*inv, f[5]*inv, f[6]*inv, f[7]*inv);
            float4* og = reinterpret_cast<float4*>(out + ((size_t)head*NSEQ + t0 + r0 + r)*DH + dg);
            og[0] = w0; og[1] = w1;
        }
    }
}

extern "C" void kernel_launch(void* const* d_in, const int* in_sizes, int n_in,
                              void* d_out, int out_size) {
    const float* q    = (const float*)d_in[0];
    const float* k    = (const float*)d_in[1];
    const float* v    = (const float*)d_in[2];
    const float* proj = (const float*)d_in[3];
    float* out = (float*)d_out;

    size_t smem_cs  = (size_t)(CH*MF + CH*DH) * sizeof(float);                       // 81920
    size_t smem_out = (size_t)(2*CH*QS + MF*DH + CH*DH + CH*SS + MF + CH) * sizeof(float); // 231936
    cudaFuncSetAttribute(chunksum_kernel, cudaFuncAttributeMaxDynamicSharedMemorySize, (int)smem_cs);
    cudaFuncSetAttribute(out_kernel,      cudaFuncAttributeMaxDynamicSharedMemorySize, (int)smem_out);

    init_kernel<<<1, 32>>>();
    proj_kernel<true ><<<BH*(NSEQ/TOK), 256>>>(q, proj);
    proj_kernel<false><<<BH*(NSEQ/TOK), 256>>>(k, proj);
    chunksum_kernel<<<BH*NC, 512, smem_cs>>>(v);
    prefix_kernel<<<dim3(BH, 65), 256>>>();
    out_kernel<<<BH*NC, 512, smem_out>>>(v, out);
}

// round 9
// speedup vs baseline: 1.5064x; 1.2426x over previous
#include <cuda_runtime.h>
#include <math.h>

#define BH   16
#define NSEQ 2048
#define DH   64
#define MF   256
#define CH   64
#define NC   (NSEQ/CH)
#define CSUM (MF*DH + MF)
#define TOK  16

#define NORMALIZER 0.35355339059327373f  // 64^-0.25
#define RATIO      0.0625f               // 256^-0.5
#define EPSK       1e-4f
#define EPSD       1e-6f

typedef unsigned long long ull;

__device__ __align__(16) float g_qp[BH*NSEQ*MF];
__device__ __align__(16) float g_kp[BH*NSEQ*MF];
__device__ __align__(16) float g_kmax[BH];
// per chunk: CtxT [d=64][m=256] then ksum[256]; exclusive-prefixed over chunks
__device__ __align__(16) float g_csum[BH*NC*CSUM];

__device__ __forceinline__ ull pack2(float lo, float hi) {
    ull r; asm("mov.b64 %0, {%1,%2};" : "=l"(r) : "f"(lo), "f"(hi)); return r;
}
__device__ __forceinline__ void fma2(ull& acc, ull a, ull b) {
    asm("fma.rn.f32x2 %0, %1, %2, %0;" : "+l"(acc) : "l"(a), "l"(b));
}
__device__ __forceinline__ float lohi(ull a) {
    float lo, hi; asm("mov.b64 {%0,%1}, %2;" : "=f"(lo), "=f"(hi) : "l"(a)); return lo + hi;
}

__device__ __forceinline__ unsigned f2tf(float f) {
    unsigned u; asm("cvt.rna.tf32.f32 %0, %1;" : "=r"(u) : "f"(f)); return u;
}
// D += A*B, m16n8k8 tf32. Fragments filled manually (k-permuted pairing).
__device__ __forceinline__ void mma8(float c[4], unsigned a0, unsigned a1,
                                     unsigned a2, unsigned a3,
                                     unsigned b0, unsigned b1) {
    asm("mma.sync.aligned.m16n8k8.row.col.f32.tf32.tf32.f32 "
        "{%0,%1,%2,%3},{%4,%5,%6,%7},{%8,%9},{%0,%1,%2,%3};"
        : "+f"(c[0]), "+f"(c[1]), "+f"(c[2]), "+f"(c[3])
        : "r"(a0), "r"(a1), "r"(a2), "r"(a3), "r"(b0), "r"(b1));
}

__device__ __forceinline__ void atomicMaxF(float* addr, float val) {
    int old = __float_as_int(*addr);
    while (val > __int_as_float(old)) {
        int assumed = old;
        old = atomicCAS((int*)addr, assumed, __float_as_int(val));
        if (old == assumed) break;
    }
}

__global__ void init_kernel() {
    if (threadIdx.x < BH) g_kmax[threadIdx.x] = -3.0e38f;
}

// ---------------- proj (unchanged from R8, fp32) ----------------
template<bool IS_Q>
__global__ __launch_bounds__(256) void proj_kernel(const float* __restrict__ x,
                                                   const float* __restrict__ proj) {
    int blk  = blockIdx.x;
    int head = blk / (NSEQ/TOK);
    int t0   = (blk % (NSEQ/TOK)) * TOK;
    int tid  = threadIdx.x;
    int wid  = tid >> 5, lane = tid & 31;

    __shared__ __align__(16) float x_s[TOK*DH];
    __shared__ float diag_s[TOK];
    __shared__ float red_s[TOK*8];
    __shared__ float mx_s[TOK];

    ull pr2[32];
    const ull* p8 = reinterpret_cast<const ull*>(proj + tid*DH);
#pragma unroll
    for (int j = 0; j < 32; j++) pr2[j] = p8[j];

    const float* xb = x + ((size_t)head*NSEQ + t0)*DH;
    for (int i = tid; i < TOK*DH; i += 256) x_s[i] = NORMALIZER * xb[i];
    __syncthreads();
    if (tid < TOK) {
        float s = 0.f;
#pragma unroll
        for (int d = 0; d < DH; d++) { float vv = x_s[tid*DH + d]; s += vv*vv; }
        diag_s[tid] = 0.5f * s;
    }
    __syncthreads();

    ull acc2[TOK];
#pragma unroll
    for (int t = 0; t < TOK; t++) acc2[t] = 0ull;
#pragma unroll 4
    for (int j = 0; j < 32; j++) {
        ull pv = pr2[j];
#pragma unroll
        for (int t = 0; t < TOK; t++) {
            ull xv = *reinterpret_cast<const ull*>(x_s + t*DH + 2*j);
            fma2(acc2[t], xv, pv);
        }
    }
    float a[TOK];
#pragma unroll
    for (int t = 0; t < TOK; t++) a[t] = lohi(acc2[t]);

    float* outp = (IS_Q ? g_qp : g_kp) + ((size_t)head*NSEQ + t0)*MF + tid;
    if (IS_Q) {
#pragma unroll
        for (int t = 0; t < TOK; t++) {
            float w = a[t];
#pragma unroll
            for (int o = 16; o >= 1; o >>= 1) w = fmaxf(w, __shfl_xor_sync(0xffffffffu, w, o));
            if (lane == 0) red_s[t*8 + wid] = w;
        }
        __syncthreads();
        if (tid < TOK) {
            float mx = red_s[tid*8];
#pragma unroll
            for (int r = 1; r < 8; r++) mx = fmaxf(mx, red_s[tid*8 + r]);
            mx_s[tid] = mx;
        }
        __syncthreads();
#pragma unroll
        for (int t = 0; t < TOK; t++)
            outp[t*MF] = RATIO * (__expf(a[t] - diag_s[t] - mx_s[t]) + EPSK);
    } else {
        float lm = a[0];
#pragma unroll
        for (int t = 1; t < TOK; t++) lm = fmaxf(lm, a[t]);
#pragma unroll
        for (int t = 0; t < TOK; t++) outp[t*MF] = a[t] - diag_s[t];
#pragma unroll
        for (int o = 16; o >= 1; o >>= 1) lm = fmaxf(lm, __shfl_xor_sync(0xffffffffu, lm, o));
        if (lane == 0) red_s[wid] = lm;
        __syncthreads();
        if (tid == 0) {
            float mx = red_s[0];
            for (int r = 1; r < 8; r++) mx = fmaxf(mx, red_s[r]);
            atomicMaxF(&g_kmax[head], mx);
        }
    }
}

// ---------------- chunksum: tf32 mma ----------------
// CtxT[d][m] = sum_t V[t][d] * phi[t][m];   ksum[m] = sum_t phi[t][m]
__global__ __launch_bounds__(256) void chunksum_kernel(const float* __restrict__ v) {
    int head = blockIdx.x / NC, c = blockIdx.x % NC, t0 = c*CH, tid = threadIdx.x;
    extern __shared__ unsigned cs_u[];
    unsigned* uphi = cs_u;            // [256][72] tf32, [m][t]
    unsigned* uvT  = cs_u + 256*72;   // [64][72]  tf32, [d][t]

    const float* vb = v + ((size_t)head*NSEQ + t0)*DH;
    for (int i = tid; i < CH*DH; i += 256) {
        int t = i >> 6, d = i & 63;
        uvT[d*72 + t] = f2tf(vb[i]);
    }
    float kmax = g_kmax[head];
    float* kpb = g_kp + ((size_t)head*NSEQ + t0)*MF;
    for (int i = tid; i < CH*MF; i += 256) {
        int t = i >> 8, m = i & 255;
        float phi = RATIO * (__expf(kpb[i] - kmax) + EPSK);
        kpb[i] = phi;
        uphi[m*72 + t] = f2tf(phi);
    }
    __syncthreads();

    int lane = tid & 31, warp = tid >> 5, gid = lane >> 2, tg = lane & 3;
    int mt = warp >> 1, nh = warp & 1;   // warp: d-tile mt, feature half nh

    float acc[16][4];
#pragma unroll
    for (int j = 0; j < 16; j++)
#pragma unroll
        for (int r = 0; r < 4; r++) acc[j][r] = 0.f;

#pragma unroll
    for (int k0 = 0; k0 < CH; k0 += 8) {
        uint2 a01 = *(const uint2*)&uvT[(mt*16 + gid    )*72 + k0 + 2*tg];
        uint2 a23 = *(const uint2*)&uvT[(mt*16 + gid + 8)*72 + k0 + 2*tg];
#pragma unroll
        for (int j = 0; j < 16; j++) {
            int m0 = (nh*16 + j)*8;
            uint2 bb = *(const uint2*)&uphi[(m0 + gid)*72 + k0 + 2*tg];
            mma8(acc[j], a01.x, a23.x, a01.y, a23.y, bb.x, bb.y);
        }
    }
    float* ob = g_csum + (size_t)(head*NC + c)*CSUM;
#pragma unroll
    for (int j = 0; j < 16; j++) {
        int m = (nh*16 + j)*8 + 2*tg;
        int d = mt*16 + gid;
        *(float2*)&ob[(size_t)d*MF + m]       = make_float2(acc[j][0], acc[j][1]);
        *(float2*)&ob[(size_t)(d + 8)*MF + m] = make_float2(acc[j][2], acc[j][3]);
    }
    // ksum (SIMT, xor-staggered reads)
    if (tid < MF) {
        float s = 0.f;
#pragma unroll 8
        for (int tt = 0; tt < CH; tt++)
            s += __uint_as_float(uphi[tid*72 + (tt ^ (tid >> 2 & 7))]);
        ob[MF*DH + tid] = s;
    }
}

// Exclusive prefix over chunks. grid (BH, 65), elementwise -> layout-agnostic.
__global__ __launch_bounds__(256) void prefix_kernel() {
    int head = blockIdx.x;
    int idx  = blockIdx.y*256 + threadIdx.x;   // 65*256 = CSUM
    float* base = g_csum + (size_t)head*NC*CSUM + idx;
    float vals[NC];
#pragma unroll
    for (int cc = 0; cc < NC; cc++) vals[cc] = base[(size_t)cc*CSUM];
    float run = 0.f;
#pragma unroll
    for (int cc = 0; cc < NC; cc++) { base[(size_t)cc*CSUM] = run; run += vals[cc]; }
}

// ---------------- out: tf32 mma, den folded as extra row ----------------
__global__ __launch_bounds__(256) void out_kernel(const float* __restrict__ v,
                                                  float* __restrict__ out) {
    int head = blockIdx.x / NC, c = blockIdx.x % NC, t0 = c*CH, tid = threadIdx.x;
    extern __shared__ unsigned osm[];
    unsigned* uq  = osm;            // [64][264] tf32 Q'  (token x feature)
    unsigned* upT = osm + 16896;    // [80][264] PT+spref row; first 64 rows alias K' in phase 1
    unsigned* uvT = osm + 38016;    // [80][72]  VT + ones row
    unsigned* uS  = osm + 43776;    // [64][72]  masked S^T, [key][q]
    unsigned* uk  = upT;

    const float* qg = g_qp + ((size_t)head*NSEQ + t0)*MF;
    const float* kg = g_kp + ((size_t)head*NSEQ + t0)*MF;
    for (int i = tid; i < CH*MF; i += 256) {
        int t = i >> 8, m = i & 255;
        uq[t*264 + m] = f2tf(qg[i]);
        uk[t*264 + m] = f2tf(kg[i]);
    }
    const float* vb = v + ((size_t)head*NSEQ + t0)*DH;
    for (int i = tid; i < CH*DH; i += 256) {
        int t = i >> 6, d = i & 63;
        uvT[d*72 + t] = f2tf(vb[i]);
    }
    for (int i = tid; i < 16*72; i += 256) {      // rows 64..79
        int r = 64 + i/72, t = i % 72;
        uvT[r*72 + t] = (r == 64 && t < CH) ? 0x3f800000u : 0u;
    }
    __syncthreads();

    int lane = tid & 31, warp = tid >> 5, gid = lane >> 2, tg = lane & 3;

    // ---- phase 1: S^T[key][q] = sum_f K'[key][f] Q'[q][f], causal-masked ----
    {
        int mt = warp >> 1, nh = warp & 1;
        float sacc[4][4];
#pragma unroll
        for (int j = 0; j < 4; j++)
#pragma unroll
            for (int r = 0; r < 4; r++) sacc[j][r] = 0.f;

#pragma unroll 4
        for (int k0 = 0; k0 < MF; k0 += 8) {
            uint2 a01 = *(const uint2*)&uk[(mt*16 + gid    )*264 + k0 + 2*tg];
            uint2 a23 = *(const uint2*)&uk[(mt*16 + gid + 8)*264 + k0 + 2*tg];
#pragma unroll
            for (int j = 0; j < 4; j++) {
                int q0 = nh*32 + j*8;
                uint2 bb = *(const uint2*)&uq[(q0 + gid)*264 + k0 + 2*tg];
                mma8(sacc[j], a01.x, a23.x, a01.y, a23.y, bb.x, bb.y);
            }
        }
#pragma unroll
        for (int j = 0; j < 4; j++) {
            int q0  = nh*32 + j*8 + 2*tg;
            int key = mt*16 + gid;
            unsigned m00 = (key     <= q0    ) ? f2tf(sacc[j][0]) : 0u;
            unsigned m01 = (key     <= q0 + 1) ? f2tf(sacc[j][1]) : 0u;
            unsigned m10 = (key + 8 <= q0    ) ? f2tf(sacc[j][2]) : 0u;
            unsigned m11 = (key + 8 <= q0 + 1) ? f2tf(sacc[j][3]) : 0u;
            *(uint2*)&uS[(key    )*72 + q0] = make_uint2(m00, m01);
            *(uint2*)&uS[(key + 8)*72 + q0] = make_uint2(m10, m11);
        }
    }
    __syncthreads();

    // stage P^T (+ spref+eps row 64, zeros 65..79) over the K' region
    const float* pb = g_csum + (size_t)(head*NC + c)*CSUM;
    for (int i = tid; i < MF*DH; i += 256) {
        int d = i >> 8, m = i & 255;
        upT[d*264 + m] = f2tf(pb[i]);
    }
    for (int m = tid; m < MF; m += 256) upT[64*264 + m] = f2tf(pb[MF*DH + m] + EPSD);
    for (int i = tid; i < 15*MF; i += 256) {
        int r = 65 + i/MF, m = i % MF;
        upT[r*264 + m] = 0u;
    }
    __syncthreads();

    // ---- phase 2: O^T[d][q] = VT_ext @ S^T + PT_ext @ Q'^T ; row 64 = den ----
    {
        int q0 = warp * 8;
        float co[5][4];
#pragma unroll
        for (int mt = 0; mt < 5; mt++)
#pragma unroll
            for (int r = 0; r < 4; r++) co[mt][r] = 0.f;

#pragma unroll
        for (int k0 = 0; k0 < CH; k0 += 8) {           // V·S term
            unsigned b0 = uS[(k0 + 2*tg    )*72 + q0 + gid];
            unsigned b1 = uS[(k0 + 2*tg + 1)*72 + q0 + gid];
#pragma unroll
            for (int mt = 0; mt < 5; mt++) {
                uint2 a01 = *(const uint2*)&uvT[(mt*16 + gid    )*72 + k0 + 2*tg];
                uint2 a23 = *(const uint2*)&uvT[(mt*16 + gid + 8)*72 + k0 + 2*tg];
                mma8(co[mt], a01.x, a23.x, a01.y, a23.y, b0, b1);
            }
        }
#pragma unroll 4
        for (int k0 = 0; k0 < MF; k0 += 8) {           // P·Q term
            uint2 bb = *(const uint2*)&uq[(q0 + gid)*264 + k0 + 2*tg];
#pragma unroll
            for (int mt = 0; mt < 5; mt++) {
                uint2 a01 = *(const uint2*)&upT[(mt*16 + gid    )*264 + k0 + 2*tg];
                uint2 a23 = *(const uint2*)&upT[(mt*16 + gid + 8)*264 + k0 + 2*tg];
                mma8(co[mt], a01.x, a23.x, a01.y, a23.y, bb.x, bb.y);
            }
        }
        // den = row 64 -> lanes (gid==0); broadcast within warp
        float den0 = __shfl_sync(0xffffffffu, co[4][0], tg);
        float den1 = __shfl_sync(0xffffffffu, co[4][1], tg);
        float i0 = 1.f/den0, i1 = 1.f/den1;
        float* ob = out + ((size_t)head*NSEQ + t0)*DH;
        int q = q0 + 2*tg;
#pragma unroll
        for (int mt = 0; mt < 4; mt++) {
            int d = mt*16 + gid;
            ob[(size_t)(q    )*DH + d    ] = co[mt][0]*i0;
            ob[(size_t)(q + 1)*DH + d    ] = co[mt][1]*i1;
            ob[(size_t)(q    )*DH + d + 8] = co[mt][2]*i0;
            ob[(size_t)(q + 1)*DH + d + 8] = co[mt][3]*i1;
        }
    }
}

extern "C" void kernel_launch(void* const* d_in, const int* in_sizes, int n_in,
                              void* d_out, int out_size) {
    const float* q    = (const float*)d_in[0];
    const float* k    = (const float*)d_in[1];
    const float* v    = (const float*)d_in[2];
    const float* proj = (const float*)d_in[3];
    float* out = (float*)d_out;

    size_t smem_cs  = (size_t)(256*72 + 64*72) * sizeof(unsigned);                  // 92160
    size_t smem_out = (size_t)(16896 + 21120 + 5760 + 4608) * sizeof(unsigned);     // 193536
    cudaFuncSetAttribute(chunksum_kernel, cudaFuncAttributeMaxDynamicSharedMemorySize, (int)smem_cs);
    cudaFuncSetAttribute(out_kernel,      cudaFuncAttributeMaxDynamicSharedMemorySize, (int)smem_out);

    init_kernel<<<1, 32>>>();
    proj_kernel<true ><<<BH*(NSEQ/TOK), 256>>>(q, proj);
    proj_kernel<false><<<BH*(NSEQ/TOK), 256>>>(k, proj);
    chunksum_kernel<<<BH*NC, 256, smem_cs>>>(v);
    prefix_kernel<<<dim3(BH, 65), 256>>>();
    out_kernel<<<BH*NC, 256, smem_out>>>(v, out);
}

// round 10
// speedup vs baseline: 2.5296x; 1.6793x over previous
#include <cuda_runtime.h>
#include <math.h>

#define BH   16
#define NSEQ 2048
#define DH   64
#define MF   256
#define CH   64
#define NC   (NSEQ/CH)
#define CSUM (MF*DH + MF)

#define NORMALIZER 0.35355339059327373f  // 64^-0.25
#define RATIO      0.0625f               // 256^-0.5
#define EPSK       1e-4f
#define EPSD       1e-6f

typedef unsigned long long ull;

__device__ __align__(16) float g_qp[BH*NSEQ*MF];
__device__ __align__(16) float g_kp[BH*NSEQ*MF];   // holds xd - diag until chunksum applies exp
__device__ __align__(16) float g_kmax[BH];
// per chunk: CtxT [d=64][m=256] then ksum[256]; exclusive-prefixed over chunks
__device__ __align__(16) float g_csum[BH*NC*CSUM];

__device__ __forceinline__ unsigned f2tf(float f) {
    unsigned u; asm("cvt.rna.tf32.f32 %0, %1;" : "=r"(u) : "f"(f)); return u;
}
__device__ __forceinline__ void mma8(float c[4], unsigned a0, unsigned a1,
                                     unsigned a2, unsigned a3,
                                     unsigned b0, unsigned b1) {
    asm("mma.sync.aligned.m16n8k8.row.col.f32.tf32.tf32.f32 "
        "{%0,%1,%2,%3},{%4,%5,%6,%7},{%8,%9},{%0,%1,%2,%3};"
        : "+f"(c[0]), "+f"(c[1]), "+f"(c[2]), "+f"(c[3])
        : "r"(a0), "r"(a1), "r"(a2), "r"(a3), "r"(b0), "r"(b1));
}
__device__ __forceinline__ void atomicMaxF(float* addr, float val) {
    int old = __float_as_int(*addr);
    while (val > __int_as_float(old)) {
        int assumed = old;
        old = atomicCAS((int*)addr, assumed, __float_as_int(val));
        if (old == assumed) break;
    }
}

__global__ void init_kernel() {
    if (threadIdx.x < BH) g_kmax[threadIdx.x] = -3.0e38f;
}

// ---------------- fused proj: compensated tf32 mma, q + k passes ----------------
// Block = (head, 128-token tile). grid 16*16=256, 512 threads.
__global__ __launch_bounds__(512) void proj_kernel(const float* __restrict__ q,
                                                   const float* __restrict__ k,
                                                   const float* __restrict__ proj) {
    int head = blockIdx.x >> 4;
    int t0   = (blockIdx.x & 15) * 128;
    int tid  = threadIdx.x;
    int lane = tid & 31, warp = tid >> 5;
    int gid  = lane >> 2, tg = lane & 3;
    int mt   = warp & 7;       // token tile: rows mt*16+gid, +8
    int nh   = warp >> 3;      // feature half: tiles nh*16 + jj

    extern __shared__ unsigned psm[];
    unsigned* uph = psm;                // [256][72] proj hi
    unsigned* upl = psm + 256*72;       // [256][72] proj lo
    unsigned* uxh = psm + 2*256*72;     // [128][72] x hi
    unsigned* uxl = uxh + 128*72;       // [128][72] x lo
    __shared__ float diag_s[128];
    __shared__ float mx_s[128];
    __shared__ float red_s[256];

    // stage proj hi/lo (once)
    for (int i = tid; i < MF*DH; i += 512) {
        int r = i >> 6, d = i & 63;
        float f = proj[i];
        unsigned hi = f2tf(f);
        uph[r*72 + d] = hi;
        upl[r*72 + d] = f2tf(f - __uint_as_float(hi));
    }

#pragma unroll
    for (int pass = 0; pass < 2; pass++) {
        const float* x = (pass == 0) ? q : k;
        const float* xb = x + ((size_t)head*NSEQ + t0)*DH;
        __syncthreads();   // proj staged / previous pass done reading x smem
        for (int i = tid; i < 128*DH; i += 512) {
            int r = i >> 6, d = i & 63;
            float f = NORMALIZER * xb[i];
            unsigned hi = f2tf(f);
            uxh[r*72 + d] = hi;
            uxl[r*72 + d] = f2tf(f - __uint_as_float(hi));
        }
        __syncthreads();
        if (tid < 128) {
            float s = 0.f;
#pragma unroll 8
            for (int d = 0; d < DH; d++) {
                float vv = __uint_as_float(uxh[tid*72 + d]) + __uint_as_float(uxl[tid*72 + d]);
                s += vv*vv;
            }
            diag_s[tid] = 0.5f * s;
        }

        float acc[16][4];
#pragma unroll
        for (int j = 0; j < 16; j++)
#pragma unroll
            for (int r = 0; r < 4; r++) acc[j][r] = 0.f;

#pragma unroll
        for (int k0 = 0; k0 < DH; k0 += 8) {
            uint2 ah01 = *(const uint2*)&uxh[(mt*16 + gid    )*72 + k0 + 2*tg];
            uint2 ah23 = *(const uint2*)&uxh[(mt*16 + gid + 8)*72 + k0 + 2*tg];
            uint2 al01 = *(const uint2*)&uxl[(mt*16 + gid    )*72 + k0 + 2*tg];
            uint2 al23 = *(const uint2*)&uxl[(mt*16 + gid + 8)*72 + k0 + 2*tg];
#pragma unroll
            for (int jj = 0; jj < 16; jj++) {
                int row = (nh*16 + jj)*8 + gid;
                uint2 bh = *(const uint2*)&uph[row*72 + k0 + 2*tg];
                uint2 bl = *(const uint2*)&upl[row*72 + k0 + 2*tg];
                mma8(acc[jj], ah01.x, ah23.x, ah01.y, ah23.y, bh.x, bh.y);  // hi*hi
                mma8(acc[jj], ah01.x, ah23.x, ah01.y, ah23.y, bl.x, bl.y);  // hi*lo
                mma8(acc[jj], al01.x, al23.x, al01.y, al23.y, bh.x, bh.y);  // lo*hi
            }
        }

        int row0 = mt*16 + gid, row1 = row0 + 8;
        if (pass == 0) {
            // per-token max over this warp's features
            float m0 = -3.0e38f, m1 = -3.0e38f;
#pragma unroll
            for (int jj = 0; jj < 16; jj++) {
                m0 = fmaxf(m0, fmaxf(acc[jj][0], acc[jj][1]));
                m1 = fmaxf(m1, fmaxf(acc[jj][2], acc[jj][3]));
            }
            m0 = fmaxf(m0, __shfl_xor_sync(0xffffffffu, m0, 1));
            m0 = fmaxf(m0, __shfl_xor_sync(0xffffffffu, m0, 2));
            m1 = fmaxf(m1, __shfl_xor_sync(0xffffffffu, m1, 1));
            m1 = fmaxf(m1, __shfl_xor_sync(0xffffffffu, m1, 2));
            if (tg == 0) {
                red_s[nh*128 + row0] = m0;
                red_s[nh*128 + row1] = m1;
            }
            __syncthreads();
            if (tid < 128) mx_s[tid] = fmaxf(red_s[tid], red_s[128 + tid]);
            __syncthreads();
            float d0 = diag_s[row0] + mx_s[row0];
            float d1 = diag_s[row1] + mx_s[row1];
            float* ob = g_qp + ((size_t)head*NSEQ + t0)*MF;
#pragma unroll
            for (int jj = 0; jj < 16; jj++) {
                int f0 = (nh*16 + jj)*8 + 2*tg;
                float2 w0 = make_float2(RATIO*(__expf(acc[jj][0] - d0) + EPSK),
                                        RATIO*(__expf(acc[jj][1] - d0) + EPSK));
                float2 w1 = make_float2(RATIO*(__expf(acc[jj][2] - d1) + EPSK),
                                        RATIO*(__expf(acc[jj][3] - d1) + EPSK));
                *(float2*)&ob[(size_t)row0*MF + f0] = w0;
                *(float2*)&ob[(size_t)row1*MF + f0] = w1;
            }
        } else {
            // head-global max over raw xd
            float lm = -3.0e38f;
#pragma unroll
            for (int jj = 0; jj < 16; jj++) {
                lm = fmaxf(lm, fmaxf(fmaxf(acc[jj][0], acc[jj][1]),
                                     fmaxf(acc[jj][2], acc[jj][3])));
            }
#pragma unroll
            for (int o = 16; o >= 1; o >>= 1) lm = fmaxf(lm, __shfl_xor_sync(0xffffffffu, lm, o));
            if (lane == 0) red_s[warp] = lm;
            float d0 = diag_s[row0], d1 = diag_s[row1];
            float* ob = g_kp + ((size_t)head*NSEQ + t0)*MF;
#pragma unroll
            for (int jj = 0; jj < 16; jj++) {
                int f0 = (nh*16 + jj)*8 + 2*tg;
                *(float2*)&ob[(size_t)row0*MF + f0] = make_float2(acc[jj][0]-d0, acc[jj][1]-d0);
                *(float2*)&ob[(size_t)row1*MF + f0] = make_float2(acc[jj][2]-d1, acc[jj][3]-d1);
            }
            __syncthreads();
            if (tid == 0) {
                float mx = red_s[0];
                for (int r = 1; r < 16; r++) mx = fmaxf(mx, red_s[r]);
                atomicMaxF(&g_kmax[head], mx);
            }
        }
    }
}

// ---------------- chunksum: tf32 mma (unchanged from R9) ----------------
__global__ __launch_bounds__(256) void chunksum_kernel(const float* __restrict__ v) {
    int head = blockIdx.x / NC, c = blockIdx.x % NC, t0 = c*CH, tid = threadIdx.x;
    extern __shared__ unsigned cs_u[];
    unsigned* uphi = cs_u;            // [256][72] tf32, [m][t]
    unsigned* uvT  = cs_u + 256*72;   // [64][72]  tf32, [d][t]

    const float* vb = v + ((size_t)head*NSEQ + t0)*DH;
    for (int i = tid; i < CH*DH; i += 256) {
        int t = i >> 6, d = i & 63;
        uvT[d*72 + t] = f2tf(vb[i]);
    }
    float kmax = g_kmax[head];
    float* kpb = g_kp + ((size_t)head*NSEQ + t0)*MF;
    for (int i = tid; i < CH*MF; i += 256) {
        int t = i >> 8, m = i & 255;
        float phi = RATIO * (__expf(kpb[i] - kmax) + EPSK);
        kpb[i] = phi;
        uphi[m*72 + t] = f2tf(phi);
    }
    __syncthreads();

    int lane = tid & 31, warp = tid >> 5, gid = lane >> 2, tg = lane & 3;
    int mt = warp >> 1, nh = warp & 1;

    float acc[16][4];
#pragma unroll
    for (int j = 0; j < 16; j++)
#pragma unroll
        for (int r = 0; r < 4; r++) acc[j][r] = 0.f;

#pragma unroll
    for (int k0 = 0; k0 < CH; k0 += 8) {
        uint2 a01 = *(const uint2*)&uvT[(mt*16 + gid    )*72 + k0 + 2*tg];
        uint2 a23 = *(const uint2*)&uvT[(mt*16 + gid + 8)*72 + k0 + 2*tg];
#pragma unroll
        for (int j = 0; j < 16; j++) {
            int m0 = (nh*16 + j)*8;
            uint2 bb = *(const uint2*)&uphi[(m0 + gid)*72 + k0 + 2*tg];
            mma8(acc[j], a01.x, a23.x, a01.y, a23.y, bb.x, bb.y);
        }
    }
    float* ob = g_csum + (size_t)(head*NC + c)*CSUM;
#pragma unroll
    for (int j = 0; j < 16; j++) {
        int m = (nh*16 + j)*8 + 2*tg;
        int d = mt*16 + gid;
        *(float2*)&ob[(size_t)d*MF + m]       = make_float2(acc[j][0], acc[j][1]);
        *(float2*)&ob[(size_t)(d + 8)*MF + m] = make_float2(acc[j][2], acc[j][3]);
    }
    if (tid < MF) {
        float s = 0.f;
#pragma unroll 8
        for (int tt = 0; tt < CH; tt++)
            s += __uint_as_float(uphi[tid*72 + (tt ^ (tid >> 2 & 7))]);
        ob[MF*DH + tid] = s;
    }
}

// Exclusive prefix over chunks. grid (BH, 65).
__global__ __launch_bounds__(256) void prefix_kernel() {
    int head = blockIdx.x;
    int idx  = blockIdx.y*256 + threadIdx.x;   // 65*256 = CSUM
    float* base = g_csum + (size_t)head*NC*CSUM + idx;
    float vals[NC];
#pragma unroll
    for (int cc = 0; cc < NC; cc++) vals[cc] = base[(size_t)cc*CSUM];
    float run = 0.f;
#pragma unroll
    for (int cc = 0; cc < NC; cc++) { base[(size_t)cc*CSUM] = run; run += vals[cc]; }
}

// ---------------- out: tf32 mma, den folded as extra row (unchanged from R9) ----------------
__global__ __launch_bounds__(256) void out_kernel(const float* __restrict__ v,
                                                  float* __restrict__ out) {
    int head = blockIdx.x / NC, c = blockIdx.x % NC, t0 = c*CH, tid = threadIdx.x;
    extern __shared__ unsigned osm[];
    unsigned* uq  = osm;            // [64][264] tf32 Q'
    unsigned* upT = osm + 16896;    // [80][264] PT+spref row; aliases K' in phase 1
    unsigned* uvT = osm + 38016;    // [80][72]  VT + ones row
    unsigned* uS  = osm + 43776;    // [64][72]  masked S^T
    unsigned* uk  = upT;

    const float* qg = g_qp + ((size_t)head*NSEQ + t0)*MF;
    const float* kg = g_kp + ((size_t)head*NSEQ + t0)*MF;
    for (int i = tid; i < CH*MF; i += 256) {
        int t = i >> 8, m = i & 255;
        uq[t*264 + m] = f2tf(qg[i]);
        uk[t*264 + m] = f2tf(kg[i]);
    }
    const float* vb = v + ((size_t)head*NSEQ + t0)*DH;
    for (int i = tid; i < CH*DH; i += 256) {
        int t = i >> 6, d = i & 63;
        uvT[d*72 + t] = f2tf(vb[i]);
    }
    for (int i = tid; i < 16*72; i += 256) {
        int r = 64 + i/72, t = i % 72;
        uvT[r*72 + t] = (r == 64 && t < CH) ? 0x3f800000u : 0u;
    }
    __syncthreads();

    int lane = tid & 31, warp = tid >> 5, gid = lane >> 2, tg = lane & 3;

    {
        int mt = warp >> 1, nh = warp & 1;
        float sacc[4][4];
#pragma unroll
        for (int j = 0; j < 4; j++)
#pragma unroll
            for (int r = 0; r < 4; r++) sacc[j][r] = 0.f;

#pragma unroll 4
        for (int k0 = 0; k0 < MF; k0 += 8) {
            uint2 a01 = *(const uint2*)&uk[(mt*16 + gid    )*264 + k0 + 2*tg];
            uint2 a23 = *(const uint2*)&uk[(mt*16 + gid + 8)*264 + k0 + 2*tg];
#pragma unroll
            for (int j = 0; j < 4; j++) {
                int q0 = nh*32 + j*8;
                uint2 bb = *(const uint2*)&uq[(q0 + gid)*264 + k0 + 2*tg];
                mma8(sacc[j], a01.x, a23.x, a01.y, a23.y, bb.x, bb.y);
            }
        }
#pragma unroll
        for (int j = 0; j < 4; j++) {
            int q0  = nh*32 + j*8 + 2*tg;
            int key = mt*16 + gid;
            unsigned m00 = (key     <= q0    ) ? f2tf(sacc[j][0]) : 0u;
            unsigned m01 = (key     <= q0 + 1) ? f2tf(sacc[j][1]) : 0u;
            unsigned m10 = (key + 8 <= q0    ) ? f2tf(sacc[j][2]) : 0u;
            unsigned m11 = (key + 8 <= q0 + 1) ? f2tf(sacc[j][3]) : 0u;
            *(uint2*)&uS[(key    )*72 + q0] = make_uint2(m00, m01);
            *(uint2*)&uS[(key + 8)*72 + q0] = make_uint2(m10, m11);
        }
    }
    __syncthreads();

    const float* pb = g_csum + (size_t)(head*NC + c)*CSUM;
    for (int i = tid; i < MF*DH; i += 256) {
        int d = i >> 8, m = i & 255;
        upT[d*264 + m] = f2tf(pb[i]);
    }
    for (int m = tid; m < MF; m += 256) upT[64*264 + m] = f2tf(pb[MF*DH + m] + EPSD);
    for (int i = tid; i < 15*MF; i += 256) {
        int r = 65 + i/MF, m = i % MF;
        upT[r*264 + m] = 0u;
    }
    __syncthreads();

    {
        int q0 = warp * 8;
        float co[5][4];
#pragma unroll
        for (int mt = 0; mt < 5; mt++)
#pragma unroll
            for (int r = 0; r < 4; r++) co[mt][r] = 0.f;

#pragma unroll
        for (int k0 = 0; k0 < CH; k0 += 8) {
            unsigned b0 = uS[(k0 + 2*tg    )*72 + q0 + gid];
            unsigned b1 = uS[(k0 + 2*tg + 1)*72 + q0 + gid];
#pragma unroll
            for (int mt = 0; mt < 5; mt++) {
                uint2 a01 = *(const uint2*)&uvT[(mt*16 + gid    )*72 + k0 + 2*tg];
                uint2 a23 = *(const uint2*)&uvT[(mt*16 + gid + 8)*72 + k0 + 2*tg];
                mma8(co[mt], a01.x, a23.x, a01.y, a23.y, b0, b1);
            }
        }
#pragma unroll 4
        for (int k0 = 0; k0 < MF; k0 += 8) {
            uint2 bb = *(const uint2*)&uq[(q0 + gid)*264 + k0 + 2*tg];
#pragma unroll
            for (int mt = 0; mt < 5; mt++) {
                uint2 a01 = *(const uint2*)&upT[(mt*16 + gid    )*264 + k0 + 2*tg];
                uint2 a23 = *(const uint2*)&upT[(mt*16 + gid + 8)*264 + k0 + 2*tg];
                mma8(co[mt], a01.x, a23.x, a01.y, a23.y, bb.x, bb.y);
            }
        }
        float den0 = __shfl_sync(0xffffffffu, co[4][0], tg);
        float den1 = __shfl_sync(0xffffffffu, co[4][1], tg);
        float i0 = 1.f/den0, i1 = 1.f/den1;
        float* ob = out + ((size_t)head*NSEQ + t0)*DH;
        int qq = q0 + 2*tg;
#pragma unroll
        for (int mt = 0; mt < 4; mt++) {
            int d = mt*16 + gid;
            ob[(size_t)(qq    )*DH + d    ] = co[mt][0]*i0;
            ob[(size_t)(qq + 1)*DH + d    ] = co[mt][1]*i1;
            ob[(size_t)(qq    )*DH + d + 8] = co[mt][2]*i0;
            ob[(size_t)(qq + 1)*DH + d + 8] = co[mt][3]*i1;
        }
    }
}

extern "C" void kernel_launch(void* const* d_in, const int* in_sizes, int n_in,
                              void* d_out, int out_size) {
    const float* q    = (const float*)d_in[0];
    const float* k    = (const float*)d_in[1];
    const float* v    = (const float*)d_in[2];
    const float* proj = (const float*)d_in[3];
    float* out = (float*)d_out;

    size_t smem_pr  = (size_t)(2*256*72 + 2*128*72) * sizeof(unsigned);             // 221184
    size_t smem_cs  = (size_t)(256*72 + 64*72) * sizeof(unsigned);                  // 92160
    size_t smem_out = (size_t)(16896 + 21120 + 5760 + 4608) * sizeof(unsigned);     // 193536
    cudaFuncSetAttribute(proj_kernel,     cudaFuncAttributeMaxDynamicSharedMemorySize, (int)smem_pr);
    cudaFuncSetAttribute(chunksum_kernel, cudaFuncAttributeMaxDynamicSharedMemorySize, (int)smem_cs);
    cudaFuncSetAttribute(out_kernel,      cudaFuncAttributeMaxDynamicSharedMemorySize, (int)smem_out);

    init_kernel<<<1, 32>>>();
    proj_kernel<<<BH*16, 512, smem_pr>>>(q, k, proj);
    chunksum_kernel<<<BH*NC, 256, smem_cs>>>(v);
    prefix_kernel<<<dim3(BH, 65), 256>>>();
    out_kernel<<<BH*NC, 256, smem_out>>>(v, out);
}